// round 8
// baseline (speedup 1.0000x reference)
#include <cuda_runtime.h>
#include <cstdint>

// ---------------------------------------------------------------------------
// y = W8(...(W0 x + b0)...) + b8  ->  y = W_eff x + b_eff,  W_eff [10,784].
// R8: gemv with 2 rows/lane, 4 column-lanes, 8 row-groups per warp.
//     acc = 40 regs -> no spills under launch_bounds(256,2).
//     x double-buffered direct LDG.128; W smem broadcast amortized x16 rows.
// ---------------------------------------------------------------------------

#define K_IN   784
#define N_OUT  10

__device__ float g_A[10 * 69];
__device__ float g_beff[N_OUT];
__device__ float g_Weff[N_OUT * K_IN];

// ---------------------------------------------------------------------------
// fold_small: one block; fold W8..W1 + full bias chain (tiny FLOPs).
// ---------------------------------------------------------------------------
__device__ __forceinline__ void fold_step_sm(
    float* A, float* T, float* beff,
    const float* W, const float* b, int n, int m, int t)
{
    if (t < N_OUT) {
        float s = 0.f;
        for (int k = 0; k < n; ++k) s += A[t * n + k] * b[k];
        beff[t] += s;
    }
    if (t < N_OUT * m) {
        int r = t / m, c = t % m;
        float s = 0.f;
        for (int k = 0; k < n; ++k) s += A[r * n + k] * W[k * m + c];
        T[t] = s;
    }
    __syncthreads();
    if (t < N_OUT * m) A[t] = T[t];
    __syncthreads();
}

__global__ void fold_small(
    const float* __restrict__ b0,
    const float* __restrict__ W1, const float* __restrict__ b1,
    const float* __restrict__ W2, const float* __restrict__ b2,
    const float* __restrict__ W3, const float* __restrict__ b3,
    const float* __restrict__ W4, const float* __restrict__ b4,
    const float* __restrict__ W5, const float* __restrict__ b5,
    const float* __restrict__ W6, const float* __restrict__ b6,
    const float* __restrict__ W7, const float* __restrict__ b7,
    const float* __restrict__ W8, const float* __restrict__ b8)
{
    __shared__ float A[10 * 69], T[10 * 69], beff[N_OUT];
    __shared__ float sw[3049];
    __shared__ float sbv[170];

    const int t = threadIdx.x;
    const int nt = blockDim.x;

    float* sW1 = sw;          float* sW2 = sw + 2139;
    float* sW3 = sw + 2449;   float* sW4 = sw + 2549;
    float* sW5 = sw + 2649;   float* sW6 = sw + 2749;
    float* sW7 = sw + 2849;   float* sW8 = sw + 2949;
    float* sb0 = sbv;         float* sb1 = sbv + 69;
    float* sb2 = sbv + 100;   float* sb3 = sbv + 110;
    float* sb4 = sbv + 120;   float* sb5 = sbv + 130;
    float* sb6 = sbv + 140;   float* sb7 = sbv + 150;
    float* sb8 = sbv + 160;

    for (int i = t; i < 2139; i += nt) sW1[i] = W1[i];
    for (int i = t; i < 310;  i += nt) sW2[i] = W2[i];
    if (t < 100) { sW3[t] = W3[t]; sW4[t] = W4[t]; sW5[t] = W5[t];
                   sW6[t] = W6[t]; sW7[t] = W7[t]; sW8[t] = W8[t]; }
    if (t < 69) sb0[t] = b0[t];
    if (t < 31) sb1[t] = b1[t];
    if (t < 10) { sb2[t] = b2[t]; sb3[t] = b3[t]; sb4[t] = b4[t];
                  sb5[t] = b5[t]; sb6[t] = b6[t]; sb7[t] = b7[t];
                  sb8[t] = b8[t]; }
    __syncthreads();

    if (t < 100) A[t] = sW8[t];
    if (t < N_OUT) beff[t] = sb8[t];
    __syncthreads();

    fold_step_sm(A, T, beff, sW7, sb7, 10, 10, t);
    fold_step_sm(A, T, beff, sW6, sb6, 10, 10, t);
    fold_step_sm(A, T, beff, sW5, sb5, 10, 10, t);
    fold_step_sm(A, T, beff, sW4, sb4, 10, 10, t);
    fold_step_sm(A, T, beff, sW3, sb3, 10, 10, t);
    fold_step_sm(A, T, beff, sW2, sb2, 10, 31, t);
    fold_step_sm(A, T, beff, sW1, sb1, 31, 69, t);

    if (t < N_OUT) {
        float s = 0.f;
        for (int k = 0; k < 69; ++k) s += A[t * 69 + k] * sb0[k];
        g_beff[t] = beff[t] + s;
    }
    for (int i = t; i < 10 * 69; i += nt) g_A[i] = A[i];
}

// ---------------------------------------------------------------------------
// fold_W0: W_eff = A @ W0, parallel over 7 CTAs; W0 loads coalesced.
// ---------------------------------------------------------------------------
__global__ void fold_W0(const float* __restrict__ W0)
{
    __shared__ float sA[10 * 69];
    const int tid = threadIdx.x;
    for (int i = tid; i < 690; i += 112) sA[i] = g_A[i];
    __syncthreads();

    const int c = blockIdx.x * 112 + tid;   // 7 * 112 = 784
    float acc[N_OUT];
#pragma unroll
    for (int r = 0; r < N_OUT; ++r) acc[r] = 0.f;
#pragma unroll 4
    for (int k = 0; k < 69; ++k) {
        float w0 = W0[k * K_IN + c];
#pragma unroll
        for (int r = 0; r < N_OUT; ++r) acc[r] += sA[r * 69 + k] * w0;
    }
#pragma unroll
    for (int r = 0; r < N_OUT; ++r) g_Weff[r * K_IN + c] = acc[r];
}

// ---------------------------------------------------------------------------
// gemv_direct: grid = B/128 CTAs x 256 threads.
// warp = 4 kg-lanes (columns) x 8 rg-groups; each lane owns 2 rows.
// Per warp-iter: 16 rows x 16 cols; x via 2 direct LDG.128 (double-buffered);
// W via 10 LDS.128 (conflict-free, 8-way broadcast). acc in packed f32x2.
// 784 = 49 * 16 -> no padding, no column predicates.
// ---------------------------------------------------------------------------
__device__ __forceinline__ void ffma2(unsigned long long& acc,
                                      unsigned long long a,
                                      unsigned long long b)
{
    asm("fma.rn.f32x2 %0, %1, %2, %0;" : "+l"(acc) : "l"(a), "l"(b));
}

__global__ __launch_bounds__(256, 2) void gemv_direct(
    const float* __restrict__ x, float* __restrict__ y, int B)
{
    __shared__ float sW[N_OUT * K_IN];   // 31360 B
    __shared__ float sb[N_OUT];

    const int tid = threadIdx.x;

    for (int i = tid; i < N_OUT * K_IN; i += 256) sW[i] = g_Weff[i];
    if (tid < N_OUT) sb[tid] = g_beff[tid];
    __syncthreads();

    const int lane = tid & 31;
    const int warp = tid >> 5;
    const int kg = lane & 3;            // column lane 0..3
    const int rg = lane >> 2;           // row group 0..7
    const int row0 = blockIdx.x * 128 + warp * 16 + rg * 2;   // 2 rows/lane

    const bool r0ok = (row0 < B);
    const bool r1ok = (row0 + 1 < B);
    const float* x0 = x + (size_t)row0 * K_IN + 4 * kg;
    const float* x1 = x0 + K_IN;

    unsigned long long acc[N_OUT][2];
#pragma unroll
    for (int j = 0; j < N_OUT; ++j) { acc[j][0] = 0ull; acc[j][1] = 0ull; }

    // software-pipelined x loads: prefetch iter i+1 while computing iter i
    ulonglong2 xa, xb, xa_n, xb_n;
    xa.x = xa.y = xb.x = xb.y = 0ull;
    if (r0ok) xa = *reinterpret_cast<const ulonglong2*>(x0);
    if (r1ok) xb = *reinterpret_cast<const ulonglong2*>(x1);

#pragma unroll 1
    for (int i = 0; i < 49; ++i) {
        const int c = 4 * kg + 16 * i;

        // prefetch next
        xa_n.x = xa_n.y = xb_n.x = xb_n.y = 0ull;
        if (i < 48) {
            if (r0ok) xa_n = *reinterpret_cast<const ulonglong2*>(x0 + 16 * (i + 1));
            if (r1ok) xb_n = *reinterpret_cast<const ulonglong2*>(x1 + 16 * (i + 1));
        }

#pragma unroll
        for (int j = 0; j < N_OUT; ++j) {
            ulonglong2 w = *reinterpret_cast<const ulonglong2*>(&sW[j * K_IN + c]);
            ffma2(acc[j][0], xa.x, w.x);
            ffma2(acc[j][0], xa.y, w.y);
            ffma2(acc[j][1], xb.x, w.x);
            ffma2(acc[j][1], xb.y, w.y);
        }
        xa = xa_n; xb = xb_n;
    }

    // collapse f32x2 halves
    float s[N_OUT][2];
#pragma unroll
    for (int j = 0; j < N_OUT; ++j)
#pragma unroll
        for (int rr = 0; rr < 2; ++rr) {
            float lo, hi;
            asm("mov.b64 {%0, %1}, %2;" : "=f"(lo), "=f"(hi) : "l"(acc[j][rr]));
            s[j][rr] = lo + hi;
        }

    // butterfly reduce over 4 kg lanes (xor 1, 2 stay within rg group)
#pragma unroll
    for (int m = 1; m <= 2; m <<= 1)
#pragma unroll
        for (int j = 0; j < N_OUT; ++j)
#pragma unroll
            for (int rr = 0; rr < 2; ++rr)
                s[j][rr] += __shfl_xor_sync(0xFFFFFFFFu, s[j][rr], m);

    // stores: lane kg writes float2 pair #kg; kg==0 additionally pair #4
#pragma unroll
    for (int rr = 0; rr < 2; ++rr) {
        const int row = row0 + rr;
        if (row < B) {
            float2 v;
            v.x = s[2 * kg][rr]     + sb[2 * kg];
            v.y = s[2 * kg + 1][rr] + sb[2 * kg + 1];
            *reinterpret_cast<float2*>(y + (size_t)row * N_OUT + 2 * kg) = v;
            if (kg == 0) {
                float2 v4;
                v4.x = s[8][rr] + sb[8];
                v4.y = s[9][rr] + sb[9];
                *reinterpret_cast<float2*>(y + (size_t)row * N_OUT + 8) = v4;
            }
        }
    }
}

// ---------------------------------------------------------------------------
extern "C" void kernel_launch(void* const* d_in, const int* in_sizes, int n_in,
                              void* d_out, int out_size)
{
    const float* x = (const float*)d_in[0];
    const float* W[9];
    const float* b[9];
    for (int i = 0; i < 9; ++i) {
        W[i] = (const float*)d_in[1 + 2 * i];
        b[i] = (const float*)d_in[2 + 2 * i];
    }
    const int B = in_sizes[0] / K_IN;

    fold_small<<<1, 768>>>(b[0], W[1], b[1], W[2], b[2], W[3], b[3],
                           W[4], b[4], W[5], b[5], W[6], b[6],
                           W[7], b[7], W[8], b[8]);
    fold_W0<<<7, 112>>>(W[0]);

    float* y = (float*)d_out;
    gemv_direct<<<(B + 127) / 128, 256>>>(x, y, B);
}

// round 9
// speedup vs baseline: 1.2318x; 1.2318x over previous
#include <cuda_runtime.h>
#include <cstdint>

// ---------------------------------------------------------------------------
// y = W8(...(W0 x + b0)...) + b8  ->  y = W_eff x + b_eff,  W_eff [10,784].
// R9: gemv = 8 kg-lanes x 4 rg x 2 rows/lane (32-col single-touch x lines,
//     W-LDS amortized, 40-reg accs, occ 3, pipelined x prefetch).
//     fold = ONE 7-CTA kernel, fully unrolled steps (was 11us serial chain).
// ---------------------------------------------------------------------------

#define K_IN   784
#define N_OUT  10

__device__ float g_Weff[N_OUT * K_IN];
__device__ float g_beff[N_OUT];

// ---------------------------------------------------------------------------
// fold_fused: 7 CTAs x 768 threads. Each CTA: prefetch small weights ->
// fold A = W8..W1 (unrolled, in smem) -> compute W_eff cols [112*bid, +112).
// CTA 0 also computes b_eff.
// ---------------------------------------------------------------------------
template<int N, int M>
__device__ __forceinline__ void fold_step(float* A, float* T, float* beff,
    const float* W, const float* b, int t)
{
    if (t < N_OUT) {
        float s = 0.f;
#pragma unroll
        for (int k = 0; k < N; ++k) s += A[t * N + k] * b[k];
        beff[t] += s;
    }
    for (int idx = t; idx < N_OUT * M; idx += 768) {
        int r = idx / M, c = idx - r * M;
        float s = 0.f;
#pragma unroll
        for (int k = 0; k < N; ++k) s += A[r * N + k] * W[k * M + c];
        T[idx] = s;
    }
    __syncthreads();
    for (int idx = t; idx < N_OUT * M; idx += 768) A[idx] = T[idx];
    __syncthreads();
}

__global__ __launch_bounds__(768) void fold_fused(
    const float* __restrict__ W0, const float* __restrict__ b0,
    const float* __restrict__ W1, const float* __restrict__ b1,
    const float* __restrict__ W2, const float* __restrict__ b2,
    const float* __restrict__ W3, const float* __restrict__ b3,
    const float* __restrict__ W4, const float* __restrict__ b4,
    const float* __restrict__ W5, const float* __restrict__ b5,
    const float* __restrict__ W6, const float* __restrict__ b6,
    const float* __restrict__ W7, const float* __restrict__ b7,
    const float* __restrict__ W8, const float* __restrict__ b8)
{
    __shared__ float A[10 * 69], T[10 * 69], beff[N_OUT];
    __shared__ float sw[3049];
    __shared__ float sbv[170];

    const int t = threadIdx.x;

    float* sW1 = sw;          float* sW2 = sw + 2139;
    float* sW3 = sw + 2449;   float* sW4 = sw + 2549;
    float* sW5 = sw + 2649;   float* sW6 = sw + 2749;
    float* sW7 = sw + 2849;   float* sW8 = sw + 2949;
    float* sb0 = sbv;         float* sb1 = sbv + 69;
    float* sb2 = sbv + 100;   float* sb3 = sbv + 110;
    float* sb4 = sbv + 120;   float* sb5 = sbv + 130;
    float* sb6 = sbv + 140;   float* sb7 = sbv + 150;
    float* sb8 = sbv + 160;

    for (int i = t; i < 2139; i += 768) sW1[i] = W1[i];
    if (t < 310) sW2[t] = W2[t];
    if (t < 100) { sW3[t] = W3[t]; sW4[t] = W4[t]; sW5[t] = W5[t];
                   sW6[t] = W6[t]; sW7[t] = W7[t]; sW8[t] = W8[t]; }
    if (t < 69) sb0[t] = b0[t];
    if (t < 31) sb1[t] = b1[t];
    if (t < 10) { sb2[t] = b2[t]; sb3[t] = b3[t]; sb4[t] = b4[t];
                  sb5[t] = b5[t]; sb6[t] = b6[t]; sb7[t] = b7[t];
                  sb8[t] = b8[t]; }
    __syncthreads();

    if (t < 100) A[t] = sW8[t];
    if (t < N_OUT) beff[t] = sb8[t];
    __syncthreads();

    fold_step<10, 10>(A, T, beff, sW7, sb7, t);
    fold_step<10, 10>(A, T, beff, sW6, sb6, t);
    fold_step<10, 10>(A, T, beff, sW5, sb5, t);
    fold_step<10, 10>(A, T, beff, sW4, sb4, t);
    fold_step<10, 10>(A, T, beff, sW3, sb3, t);
    fold_step<10, 31>(A, T, beff, sW2, sb2, t);
    fold_step<31, 69>(A, T, beff, sW1, sb1, t);   // A now [10,69]

    if (blockIdx.x == 0 && t < N_OUT) {
        float s = 0.f;
#pragma unroll
        for (int k = 0; k < 69; ++k) s += A[t * 69 + k] * sb0[k];
        g_beff[t] = beff[t] + s;
    }

    // W_eff slice: threads 0..111 own one output column each, 10 accumulators
    if (t < 112) {
        const int col = blockIdx.x * 112 + t;
        float acc[N_OUT];
#pragma unroll
        for (int r = 0; r < N_OUT; ++r) acc[r] = 0.f;
#pragma unroll
        for (int k = 0; k < 69; ++k) {
            float w0 = W0[k * K_IN + col];
#pragma unroll
            for (int r = 0; r < N_OUT; ++r) acc[r] += A[r * 69 + k] * w0;
        }
#pragma unroll
        for (int r = 0; r < N_OUT; ++r) g_Weff[r * K_IN + col] = acc[r];
    }
}

// ---------------------------------------------------------------------------
// gemv_direct: grid = B/64 CTAs x 256 threads (8 warps x 8 rows = 64 rows).
// warp = 8 kg-lanes x 4 rg-groups, 2 rows/lane.
// Per 32-col iter: 2 LDG.128 (pipelined), 10 LDS.128 (8x16B conflict-free,
// 4-way bcast), 40 FFMA2. 24 full iters + kg<4 tail iter (cols 768..783).
// ---------------------------------------------------------------------------
__device__ __forceinline__ void ffma2(unsigned long long& acc,
                                      unsigned long long a,
                                      unsigned long long b)
{
    asm("fma.rn.f32x2 %0, %1, %2, %0;" : "+l"(acc) : "l"(a), "l"(b));
}

__global__ __launch_bounds__(256, 3) void gemv_direct(
    const float* __restrict__ x, float* __restrict__ y, int B)
{
    __shared__ float sW[N_OUT * K_IN + 16];   // +16 pad: tail W reads in-bounds
    __shared__ float sb[N_OUT];

    const int tid = threadIdx.x;

    for (int i = tid; i < N_OUT * K_IN; i += 256) sW[i] = g_Weff[i];
    if (tid < 16) sW[N_OUT * K_IN + tid] = 0.f;
    if (tid < N_OUT) sb[tid] = g_beff[tid];
    __syncthreads();

    const int lane = tid & 31;
    const int warp = tid >> 5;
    const int kg = lane & 7;           // column lane 0..7 (32B granule owner)
    const int rg = lane >> 3;          // row group 0..3
    const int row0 = blockIdx.x * 64 + warp * 8 + rg * 2;

    const bool r0ok = (row0 < B);
    const bool r1ok = (row0 + 1 < B);
    // clamp OOB rows to row 0: loads stay legal, stores are predicated
    const float* p0 = x + (size_t)(r0ok ? row0     : 0) * K_IN + 4 * kg;
    const float* p1 = x + (size_t)(r1ok ? row0 + 1 : 0) * K_IN + 4 * kg;

    unsigned long long acc[N_OUT][2];
#pragma unroll
    for (int j = 0; j < N_OUT; ++j) { acc[j][0] = 0ull; acc[j][1] = 0ull; }

    ulonglong2 xa = *reinterpret_cast<const ulonglong2*>(p0);
    ulonglong2 xb = *reinterpret_cast<const ulonglong2*>(p1);

#pragma unroll 1
    for (int i = 0; i < 25; ++i) {
        const int c = 4 * kg + 32 * i;

        // prefetch next iteration (iter 24 = 16-col tail: only kg<4 has data)
        ulonglong2 xa_n, xb_n;
        xa_n.x = xa_n.y = xb_n.x = xb_n.y = 0ull;
        if (i < 23) {
            xa_n = *reinterpret_cast<const ulonglong2*>(p0 + 32 * (i + 1));
            xb_n = *reinterpret_cast<const ulonglong2*>(p1 + 32 * (i + 1));
        } else if (i == 23 && kg < 4) {
            xa_n = *reinterpret_cast<const ulonglong2*>(p0 + 768);
            xb_n = *reinterpret_cast<const ulonglong2*>(p1 + 768);
        }

#pragma unroll
        for (int j = 0; j < N_OUT; ++j) {
            // tail (i==24): c up to 796; sW padded+zero -> safe, x zeros anyway
            ulonglong2 w = *reinterpret_cast<const ulonglong2*>(&sW[j * K_IN + c]);
            ffma2(acc[j][0], xa.x, w.x);
            ffma2(acc[j][0], xa.y, w.y);
            ffma2(acc[j][1], xb.x, w.x);
            ffma2(acc[j][1], xb.y, w.y);
        }
        xa = xa_n; xb = xb_n;
    }

    // collapse f32x2 halves
    float s[N_OUT][2];
#pragma unroll
    for (int j = 0; j < N_OUT; ++j)
#pragma unroll
        for (int rr = 0; rr < 2; ++rr) {
            float lo, hi;
            asm("mov.b64 {%0, %1}, %2;" : "=f"(lo), "=f"(hi) : "l"(acc[j][rr]));
            s[j][rr] = lo + hi;
        }

    // butterfly reduce over the 8 kg lanes
#pragma unroll
    for (int m = 1; m <= 4; m <<= 1)
#pragma unroll
        for (int j = 0; j < N_OUT; ++j)
#pragma unroll
            for (int rr = 0; rr < 2; ++rr)
                s[j][rr] += __shfl_xor_sync(0xFFFFFFFFu, s[j][rr], m);

    // lanes kg=0..4 write float2 pair #kg for both rows
    if (kg < 5) {
#pragma unroll
        for (int rr = 0; rr < 2; ++rr) {
            const int row = row0 + rr;
            if (row < B) {
                float2 v;
                v.x = s[2 * kg][rr]     + sb[2 * kg];
                v.y = s[2 * kg + 1][rr] + sb[2 * kg + 1];
                *reinterpret_cast<float2*>(y + (size_t)row * N_OUT + 2 * kg) = v;
            }
        }
    }
}

// ---------------------------------------------------------------------------
extern "C" void kernel_launch(void* const* d_in, const int* in_sizes, int n_in,
                              void* d_out, int out_size)
{
    const float* x = (const float*)d_in[0];
    const float* W[9];
    const float* b[9];
    for (int i = 0; i < 9; ++i) {
        W[i] = (const float*)d_in[1 + 2 * i];
        b[i] = (const float*)d_in[2 + 2 * i];
    }
    const int B = in_sizes[0] / K_IN;

    fold_fused<<<7, 768>>>(W[0], b[0], W[1], b[1], W[2], b[2], W[3], b[3],
                           W[4], b[4], W[5], b[5], W[6], b[6], W[7], b[7],
                           W[8], b[8]);

    float* y = (float*)d_out;
    gemv_direct<<<(B + 63) / 64, 256>>>(x, y, B);
}

// round 10
// speedup vs baseline: 1.4814x; 1.2026x over previous
#include <cuda_runtime.h>
#include <cstdint>

// ---------------------------------------------------------------------------
// y = W8(...(W0 x + b0)...) + b8  ->  y = W_eff x + b_eff,  W_eff [10,784].
// R10: gemv = 8 kg-lanes x 4 rg x 2 rows/lane, SCALAR FFMA accumulators
//      (20 regs vs 40) -> launch_bounds(256,4) -> 32 warps/SM, latency hidden.
// ---------------------------------------------------------------------------

#define K_IN   784
#define N_OUT  10

__device__ float g_Weff[N_OUT * K_IN];
__device__ float g_beff[N_OUT];

// ---------------------------------------------------------------------------
// fold_fused: 7 CTAs x 768 threads. Each CTA: prefetch small weights ->
// fold A = W8..W1 (unrolled, in smem) -> compute W_eff cols [112*bid, +112).
// CTA 0 also computes b_eff.
// ---------------------------------------------------------------------------
template<int N, int M>
__device__ __forceinline__ void fold_step(float* A, float* T, float* beff,
    const float* W, const float* b, int t)
{
    if (t < N_OUT) {
        float s = 0.f;
#pragma unroll
        for (int k = 0; k < N; ++k) s += A[t * N + k] * b[k];
        beff[t] += s;
    }
    for (int idx = t; idx < N_OUT * M; idx += 768) {
        int r = idx / M, c = idx - r * M;
        float s = 0.f;
#pragma unroll
        for (int k = 0; k < N; ++k) s += A[r * N + k] * W[k * M + c];
        T[idx] = s;
    }
    __syncthreads();
    for (int idx = t; idx < N_OUT * M; idx += 768) A[idx] = T[idx];
    __syncthreads();
}

__global__ __launch_bounds__(768) void fold_fused(
    const float* __restrict__ W0, const float* __restrict__ b0,
    const float* __restrict__ W1, const float* __restrict__ b1,
    const float* __restrict__ W2, const float* __restrict__ b2,
    const float* __restrict__ W3, const float* __restrict__ b3,
    const float* __restrict__ W4, const float* __restrict__ b4,
    const float* __restrict__ W5, const float* __restrict__ b5,
    const float* __restrict__ W6, const float* __restrict__ b6,
    const float* __restrict__ W7, const float* __restrict__ b7,
    const float* __restrict__ W8, const float* __restrict__ b8)
{
    __shared__ float A[10 * 69], T[10 * 69], beff[N_OUT];
    __shared__ float sw[3049];
    __shared__ float sbv[170];

    const int t = threadIdx.x;

    float* sW1 = sw;          float* sW2 = sw + 2139;
    float* sW3 = sw + 2449;   float* sW4 = sw + 2549;
    float* sW5 = sw + 2649;   float* sW6 = sw + 2749;
    float* sW7 = sw + 2849;   float* sW8 = sw + 2949;
    float* sb0 = sbv;         float* sb1 = sbv + 69;
    float* sb2 = sbv + 100;   float* sb3 = sbv + 110;
    float* sb4 = sbv + 120;   float* sb5 = sbv + 130;
    float* sb6 = sbv + 140;   float* sb7 = sbv + 150;
    float* sb8 = sbv + 160;

    for (int i = t; i < 2139; i += 768) sW1[i] = W1[i];
    if (t < 310) sW2[t] = W2[t];
    if (t < 100) { sW3[t] = W3[t]; sW4[t] = W4[t]; sW5[t] = W5[t];
                   sW6[t] = W6[t]; sW7[t] = W7[t]; sW8[t] = W8[t]; }
    if (t < 69) sb0[t] = b0[t];
    if (t < 31) sb1[t] = b1[t];
    if (t < 10) { sb2[t] = b2[t]; sb3[t] = b3[t]; sb4[t] = b4[t];
                  sb5[t] = b5[t]; sb6[t] = b6[t]; sb7[t] = b7[t];
                  sb8[t] = b8[t]; }
    __syncthreads();

    if (t < 100) A[t] = sW8[t];
    if (t < N_OUT) beff[t] = sb8[t];
    __syncthreads();

    fold_step<10, 10>(A, T, beff, sW7, sb7, t);
    fold_step<10, 10>(A, T, beff, sW6, sb6, t);
    fold_step<10, 10>(A, T, beff, sW5, sb5, t);
    fold_step<10, 10>(A, T, beff, sW4, sb4, t);
    fold_step<10, 10>(A, T, beff, sW3, sb3, t);
    fold_step<10, 31>(A, T, beff, sW2, sb2, t);
    fold_step<31, 69>(A, T, beff, sW1, sb1, t);   // A now [10,69]

    if (blockIdx.x == 0 && t < N_OUT) {
        float s = 0.f;
#pragma unroll
        for (int k = 0; k < 69; ++k) s += A[t * 69 + k] * sb0[k];
        g_beff[t] = beff[t] + s;
    }

    if (t < 112) {
        const int col = blockIdx.x * 112 + t;
        float acc[N_OUT];
#pragma unroll
        for (int r = 0; r < N_OUT; ++r) acc[r] = 0.f;
#pragma unroll
        for (int k = 0; k < 69; ++k) {
            float w0 = W0[k * K_IN + col];
#pragma unroll
            for (int r = 0; r < N_OUT; ++r) acc[r] += A[r * 69 + k] * w0;
        }
#pragma unroll
        for (int r = 0; r < N_OUT; ++r) g_Weff[r * K_IN + col] = acc[r];
    }
}

// ---------------------------------------------------------------------------
// gemv_direct: grid = B/64 CTAs x 256 threads (8 warps x 8 rows = 64 rows).
// warp = 8 kg-lanes x 4 rg-groups, 2 rows/lane.
// Per 32-col iter: 2 LDG.128 (pipelined), 10 LDS.128 (conflict-free 4-way
// bcast), 80 scalar FFMA. Scalar accs keep regs <=64 -> 4 CTAs/SM.
// ---------------------------------------------------------------------------
__global__ __launch_bounds__(256, 4) void gemv_direct(
    const float* __restrict__ x, float* __restrict__ y, int B)
{
    __shared__ float sW[N_OUT * K_IN + 16];   // +16 pad for tail W reads
    __shared__ float sb[N_OUT];

    const int tid = threadIdx.x;

    for (int i = tid; i < N_OUT * K_IN; i += 256) sW[i] = g_Weff[i];
    if (tid < 16) sW[N_OUT * K_IN + tid] = 0.f;
    if (tid < N_OUT) sb[tid] = g_beff[tid];
    __syncthreads();

    const int lane = tid & 31;
    const int warp = tid >> 5;
    const int kg = lane & 7;           // column lane 0..7 (16B granule owner)
    const int rg = lane >> 3;          // row group 0..3
    const int row0 = blockIdx.x * 64 + warp * 8 + rg * 2;

    const bool r0ok = (row0 < B);
    const bool r1ok = (row0 + 1 < B);
    const float* p0 = x + (size_t)(r0ok ? row0     : 0) * K_IN + 4 * kg;
    const float* p1 = x + (size_t)(r1ok ? row0 + 1 : 0) * K_IN + 4 * kg;

    float acc[N_OUT][2];
#pragma unroll
    for (int j = 0; j < N_OUT; ++j) { acc[j][0] = 0.f; acc[j][1] = 0.f; }

    float4 xa = *reinterpret_cast<const float4*>(p0);
    float4 xb = *reinterpret_cast<const float4*>(p1);

#pragma unroll 1
    for (int i = 0; i < 25; ++i) {
        const int c = 4 * kg + 32 * i;

        // prefetch next iteration (iter 24 = 16-col tail: only kg<4 has data)
        float4 xa_n, xb_n;
        xa_n.x = xa_n.y = xa_n.z = xa_n.w = 0.f;
        xb_n.x = xb_n.y = xb_n.z = xb_n.w = 0.f;
        if (i < 23) {
            xa_n = *reinterpret_cast<const float4*>(p0 + 32 * (i + 1));
            xb_n = *reinterpret_cast<const float4*>(p1 + 32 * (i + 1));
        } else if (i == 23 && kg < 4) {
            xa_n = *reinterpret_cast<const float4*>(p0 + 768);
            xb_n = *reinterpret_cast<const float4*>(p1 + 768);
        }

#pragma unroll
        for (int j = 0; j < N_OUT; ++j) {
            float4 w = *reinterpret_cast<const float4*>(&sW[j * K_IN + c]);
            acc[j][0] += xa.x * w.x; acc[j][0] += xa.y * w.y;
            acc[j][0] += xa.z * w.z; acc[j][0] += xa.w * w.w;
            acc[j][1] += xb.x * w.x; acc[j][1] += xb.y * w.y;
            acc[j][1] += xb.z * w.z; acc[j][1] += xb.w * w.w;
        }
        xa = xa_n; xb = xb_n;
    }

    // butterfly reduce over the 8 kg lanes
#pragma unroll
    for (int m = 1; m <= 4; m <<= 1)
#pragma unroll
        for (int j = 0; j < N_OUT; ++j)
#pragma unroll
            for (int rr = 0; rr < 2; ++rr)
                acc[j][rr] += __shfl_xor_sync(0xFFFFFFFFu, acc[j][rr], m);

    // lanes kg=0..4 write float2 pair #kg for both rows
    if (kg < 5) {
#pragma unroll
        for (int rr = 0; rr < 2; ++rr) {
            const int row = row0 + rr;
            if (row < B) {
                float2 v;
                v.x = acc[2 * kg][rr]     + sb[2 * kg];
                v.y = acc[2 * kg + 1][rr] + sb[2 * kg + 1];
                *reinterpret_cast<float2*>(y + (size_t)row * N_OUT + 2 * kg) = v;
            }
        }
    }
}

// ---------------------------------------------------------------------------
extern "C" void kernel_launch(void* const* d_in, const int* in_sizes, int n_in,
                              void* d_out, int out_size)
{
    const float* x = (const float*)d_in[0];
    const float* W[9];
    const float* b[9];
    for (int i = 0; i < 9; ++i) {
        W[i] = (const float*)d_in[1 + 2 * i];
        b[i] = (const float*)d_in[2 + 2 * i];
    }
    const int B = in_sizes[0] / K_IN;

    fold_fused<<<7, 768>>>(W[0], b[0], W[1], b[1], W[2], b[2], W[3], b[3],
                           W[4], b[4], W[5], b[5], W[6], b[6], W[7], b[7],
                           W[8], b[8]);

    float* y = (float*)d_out;
    gemv_direct<<<(B + 63) / 64, 256>>>(x, y, B);
}